// round 1
// baseline (speedup 1.0000x reference)
#include <cuda_runtime.h>

#define BB 8
#define C_IN 130
#define N_PTS 1024
#define M_TOT 4096
#define CQ 32

// ---------------- scratch (static device globals; no allocation) -------------
__device__ float g_net[(size_t)BB * C_IN * M_TOT];      // [B][130][4096]
__device__ float g_f  [(size_t)BB * CQ   * M_TOT];      // [B][32][4096]
__device__ float g_g  [(size_t)BB * CQ   * M_TOT];
__device__ float g_h  [(size_t)BB * C_IN * M_TOT];
__device__ float g_S  [(size_t)BB * M_TOT * M_TOT];     // 512 MB: S then E in place
__device__ float g_x  [(size_t)BB * C_IN * M_TOT];      // gamma*o + net
__device__ float g_x1 [(size_t)BB * 256  * M_TOT];

// ---------------- build net: tiled inputs + grid channels --------------------
__global__ void build_net(const float* __restrict__ inp) {
    int idx = blockIdx.x * blockDim.x + threadIdx.x;
    if (idx >= BB * C_IN * M_TOT) return;
    int m = idx % M_TOT;
    int c = (idx / M_TOT) % C_IN;
    int b = idx / (M_TOT * C_IN);
    float v;
    if (c < 128) {
        v = inp[((size_t)b * 128 + c) * N_PTS + (m & (N_PTS - 1))];
    } else {
        int u = m >> 10;                       // 0..3
        if (c == 128) v = (u & 2) ? 0.2f : -0.2f;
        else          v = (u & 1) ? 0.2f : -0.2f;
    }
    g_net[idx] = v;
}

// ---------------- generic conv1x1 + relu: Y = relu(W @ X + b) ----------------
// W: [O x K] row-major, X: [K x 4096] per batch, Y: [O x 4096] per batch
// block tile 64(O) x 64(M), BK=16, 256 threads, 4x4 per thread
__global__ __launch_bounds__(256)
void gemm_relu(const float* __restrict__ W, const float* __restrict__ bias,
               const float* __restrict__ X, float* __restrict__ Y,
               int O, int K) {
    __shared__ float As[16][68];   // As[k][o], padded
    __shared__ float Bs[16][64];
    int b  = blockIdx.z;
    const float* Xb = X + (size_t)b * K * M_TOT;
    float*       Yb = Y + (size_t)b * O * M_TOT;
    int o0 = blockIdx.y * 64, m0 = blockIdx.x * 64;
    int tid = threadIdx.x, tx = tid & 15, ty = tid >> 4;
    float acc[4][4] = {};
    for (int k0 = 0; k0 < K; k0 += 16) {
        #pragma unroll
        for (int i = 0; i < 4; i++) {
            int t = tid + i * 256;             // 0..1023
            int ro = t >> 4, rk = t & 15;
            int oo = o0 + ro, kk = k0 + rk;
            As[rk][ro] = (oo < O && kk < K) ? W[(size_t)oo * K + kk] : 0.f;
        }
        {
            int rk = tid >> 4, cm = (tid & 15) * 4;
            int kk = k0 + rk;
            float4 v = make_float4(0.f, 0.f, 0.f, 0.f);
            if (kk < K) v = *(const float4*)&Xb[(size_t)kk * M_TOT + m0 + cm];
            *(float4*)&Bs[rk][cm] = v;
        }
        __syncthreads();
        #pragma unroll
        for (int kk = 0; kk < 16; kk++) {
            float a[4], bv[4];
            *(float4*)a  = *(const float4*)&As[kk][ty * 4];
            *(float4*)bv = *(const float4*)&Bs[kk][tx * 4];
            #pragma unroll
            for (int i = 0; i < 4; i++)
                #pragma unroll
                for (int j = 0; j < 4; j++) acc[i][j] += a[i] * bv[j];
        }
        __syncthreads();
    }
    #pragma unroll
    for (int i = 0; i < 4; i++) {
        int oo = o0 + ty * 4 + i;
        if (oo < O) {
            float bvv = bias[oo];
            float4 r;
            r.x = fmaxf(acc[i][0] + bvv, 0.f);
            r.y = fmaxf(acc[i][1] + bvv, 0.f);
            r.z = fmaxf(acc[i][2] + bvv, 0.f);
            r.w = fmaxf(acc[i][3] + bvv, 0.f);
            *(float4*)&Yb[(size_t)oo * M_TOT + m0 + tx * 4] = r;
        }
    }
}

// ---------------- S = g^T f  (K=32), 64x64 tiles ------------------------------
__global__ __launch_bounds__(256)
void sgemm_s() {
    __shared__ float Gs[32][68];    // g[c][k-tile]
    __shared__ float Fs[32][64];    // f[c][m-tile]
    int b = blockIdx.z;
    const float* gb = g_g + (size_t)b * CQ * M_TOT;
    const float* fb = g_f + (size_t)b * CQ * M_TOT;
    float*       Sb = g_S + (size_t)b * M_TOT * M_TOT;
    int k0 = blockIdx.y * 64, m0 = blockIdx.x * 64;
    int tid = threadIdx.x, tx = tid & 15, ty = tid >> 4;
    #pragma unroll
    for (int i = 0; i < 2; i++) {
        int t = tid + i * 256;                 // 0..511, one float4 each
        int c = t >> 4, col = (t & 15) * 4;
        *(float4*)&Gs[c][col] = *(const float4*)&gb[(size_t)c * M_TOT + k0 + col];
        *(float4*)&Fs[c][col] = *(const float4*)&fb[(size_t)c * M_TOT + m0 + col];
    }
    __syncthreads();
    float acc[4][4] = {};
    #pragma unroll
    for (int c = 0; c < 32; c++) {
        float a[4], bv[4];
        *(float4*)a  = *(const float4*)&Gs[c][ty * 4];
        *(float4*)bv = *(const float4*)&Fs[c][tx * 4];
        #pragma unroll
        for (int i = 0; i < 4; i++)
            #pragma unroll
            for (int j = 0; j < 4; j++) acc[i][j] += a[i] * bv[j];
    }
    #pragma unroll
    for (int i = 0; i < 4; i++) {
        int kr = k0 + ty * 4 + i;
        *(float4*)&Sb[(size_t)kr * M_TOT + m0 + tx * 4] =
            make_float4(acc[i][0], acc[i][1], acc[i][2], acc[i][3]);
    }
}

// ---------------- per-row softmax in place: E = exp(S - max)/Z ----------------
__global__ __launch_bounds__(256)
void softmax_rows() {
    float* p = g_S + (size_t)blockIdx.x * M_TOT;
    int tid = threadIdx.x;
    float4 v[4];
    float lm = -3.4e38f;
    #pragma unroll
    for (int i = 0; i < 4; i++) {
        v[i] = *(float4*)&p[(i * 256 + tid) * 4];
        lm = fmaxf(lm, fmaxf(fmaxf(v[i].x, v[i].y), fmaxf(v[i].z, v[i].w)));
    }
    __shared__ float red[256];
    red[tid] = lm; __syncthreads();
    #pragma unroll
    for (int s = 128; s > 0; s >>= 1) {
        if (tid < s) red[tid] = fmaxf(red[tid], red[tid + s]);
        __syncthreads();
    }
    float mx = red[0];
    __syncthreads();
    float ls = 0.f;
    #pragma unroll
    for (int i = 0; i < 4; i++) {
        v[i].x = __expf(v[i].x - mx); v[i].y = __expf(v[i].y - mx);
        v[i].z = __expf(v[i].z - mx); v[i].w = __expf(v[i].w - mx);
        ls += v[i].x + v[i].y + v[i].z + v[i].w;
    }
    red[tid] = ls; __syncthreads();
    #pragma unroll
    for (int s = 128; s > 0; s >>= 1) {
        if (tid < s) red[tid] += red[tid + s];
        __syncthreads();
    }
    float inv = 1.0f / red[0];
    #pragma unroll
    for (int i = 0; i < 4; i++) {
        v[i].x *= inv; v[i].y *= inv; v[i].z *= inv; v[i].w *= inv;
        *(float4*)&p[(i * 256 + tid) * 4] = v[i];
    }
}

// ---------------- hot GEMM: x[0:128,:] = gamma*(h@E) + net --------------------
// tile 128(rows) x 64(cols), BK=16, 256 thr, 8x4 per thread. rows 0..127 only.
__global__ __launch_bounds__(256)
void attn_gemm(const float* __restrict__ gamma_p) {
    __shared__ float As[16][132];   // As[k][row]
    __shared__ float Bs[16][64];
    int b  = blockIdx.z;
    int m0 = blockIdx.x * 64;
    const float* Ab   = g_h   + (size_t)b * C_IN * M_TOT;
    const float* Eb   = g_S   + (size_t)b * M_TOT * M_TOT;
    const float* netb = g_net + (size_t)b * C_IN * M_TOT;
    float*       xb   = g_x   + (size_t)b * C_IN * M_TOT;
    int tid = threadIdx.x, tx = tid & 15, ty = tid >> 4;
    float acc[8][4] = {};
    for (int k0 = 0; k0 < M_TOT; k0 += 16) {
        #pragma unroll
        for (int i = 0; i < 2; i++) {
            int t = tid + i * 256;              // 0..511
            int r = t >> 2, kq = (t & 3) * 4;
            float4 av = *(const float4*)&Ab[(size_t)r * M_TOT + k0 + kq];
            As[kq + 0][r] = av.x; As[kq + 1][r] = av.y;
            As[kq + 2][r] = av.z; As[kq + 3][r] = av.w;
        }
        {
            int rk = tid >> 4, cm = (tid & 15) * 4;
            *(float4*)&Bs[rk][cm] =
                *(const float4*)&Eb[(size_t)(k0 + rk) * M_TOT + m0 + cm];
        }
        __syncthreads();
        #pragma unroll
        for (int kk = 0; kk < 16; kk++) {
            float a[8], bv[4];
            *(float4*)&a[0] = *(const float4*)&As[kk][ty * 8];
            *(float4*)&a[4] = *(const float4*)&As[kk][ty * 8 + 4];
            *(float4*)bv    = *(const float4*)&Bs[kk][tx * 4];
            #pragma unroll
            for (int i = 0; i < 8; i++)
                #pragma unroll
                for (int j = 0; j < 4; j++) acc[i][j] += a[i] * bv[j];
        }
        __syncthreads();
    }
    float gamma = __ldg(gamma_p);
    #pragma unroll
    for (int i = 0; i < 8; i++) {
        int r = ty * 8 + i;
        float4 nv = *(const float4*)&netb[(size_t)r * M_TOT + m0 + tx * 4];
        float4 o;
        o.x = gamma * acc[i][0] + nv.x;
        o.y = gamma * acc[i][1] + nv.y;
        o.z = gamma * acc[i][2] + nv.z;
        o.w = gamma * acc[i][3] + nv.w;
        *(float4*)&xb[(size_t)r * M_TOT + m0 + tx * 4] = o;
    }
}

// ---------------- tail rows 128,129 (grid channels of h): memory-bound --------
__global__ __launch_bounds__(128)
void attn_tail(const float* __restrict__ gamma_p) {
    __shared__ float h0s[M_TOT];
    __shared__ float h1s[M_TOT];
    int b  = blockIdx.y;
    int m  = blockIdx.x * 128 + threadIdx.x;
    const float* hb = g_h + (size_t)b * C_IN * M_TOT;
    const float* Eb = g_S + (size_t)b * M_TOT * M_TOT;
    for (int i = threadIdx.x; i < M_TOT / 4; i += 128) {
        ((float4*)h0s)[i] = ((const float4*)(hb + (size_t)128 * M_TOT))[i];
        ((float4*)h1s)[i] = ((const float4*)(hb + (size_t)129 * M_TOT))[i];
    }
    __syncthreads();
    float a0 = 0.f, a1 = 0.f;
    const float* ep = Eb + m;
    #pragma unroll 8
    for (int k = 0; k < M_TOT; k++) {
        float e = ep[(size_t)k * M_TOT];
        a0 += h0s[k] * e;
        a1 += h1s[k] * e;
    }
    float gamma = __ldg(gamma_p);
    const float* netb = g_net + (size_t)b * C_IN * M_TOT;
    float*       xb   = g_x   + (size_t)b * C_IN * M_TOT;
    xb[(size_t)128 * M_TOT + m] = gamma * a0 + netb[(size_t)128 * M_TOT + m];
    xb[(size_t)129 * M_TOT + m] = gamma * a1 + netb[(size_t)129 * M_TOT + m];
}

// ---------------- launch ------------------------------------------------------
extern "C" void kernel_launch(void* const* d_in, const int* in_sizes, int n_in,
                              void* d_out, int out_size) {
    const float* inputs = (const float*)d_in[0];
    const float* WF = (const float*)d_in[1];
    const float* bF = (const float*)d_in[2];
    const float* WG = (const float*)d_in[3];
    const float* bG = (const float*)d_in[4];
    const float* WH = (const float*)d_in[5];
    const float* bH = (const float*)d_in[6];
    const float* gamma = (const float*)d_in[7];
    const float* W1 = (const float*)d_in[8];
    const float* b1 = (const float*)d_in[9];
    const float* W2 = (const float*)d_in[10];
    const float* b2 = (const float*)d_in[11];
    float* out = (float*)d_out;

    void *pnet, *pf, *pg, *ph, *px, *px1;
    cudaGetSymbolAddress(&pnet, g_net);
    cudaGetSymbolAddress(&pf,   g_f);
    cudaGetSymbolAddress(&pg,   g_g);
    cudaGetSymbolAddress(&ph,   g_h);
    cudaGetSymbolAddress(&px,   g_x);
    cudaGetSymbolAddress(&px1,  g_x1);

    dim3 blk(256);

    build_net<<<(BB * C_IN * M_TOT + 255) / 256, 256>>>(inputs);

    // f, g, h
    gemm_relu<<<dim3(M_TOT / 64, 1, BB), blk>>>(WF, bF, (const float*)pnet,
                                                (float*)pf, CQ, C_IN);
    gemm_relu<<<dim3(M_TOT / 64, 1, BB), blk>>>(WG, bG, (const float*)pnet,
                                                (float*)pg, CQ, C_IN);
    gemm_relu<<<dim3(M_TOT / 64, 3, BB), blk>>>(WH, bH, (const float*)pnet,
                                                (float*)ph, C_IN, C_IN);

    // S = g^T f
    sgemm_s<<<dim3(M_TOT / 64, M_TOT / 64, BB), blk>>>();

    // softmax rows in place
    softmax_rows<<<BB * M_TOT, 256>>>();

    // x = gamma * (h @ E) + net
    attn_gemm<<<dim3(M_TOT / 64, 1, BB), blk>>>(gamma);
    attn_tail<<<dim3(M_TOT / 128, BB), 128>>>(gamma);

    // x1 = relu(W1 @ x + b1), out = relu(W2 @ x1 + b2)
    gemm_relu<<<dim3(M_TOT / 64, 4, BB), blk>>>(W1, b1, (const float*)px,
                                                (float*)px1, 256, C_IN);
    gemm_relu<<<dim3(M_TOT / 64, 2, BB), blk>>>(W2, b2, (const float*)px1,
                                                out, 128, 256);
}

// round 10
// speedup vs baseline: 1.7411x; 1.7411x over previous
#include <cuda_runtime.h>
#include <cuda_bf16.h>
#include <mma.h>

using namespace nvcuda;

#define BB 8
#define C_IN 130
#define N_PTS 1024
#define M_TOT 4096
#define CQ 32

typedef __nv_bfloat16 bf16;

// ---------------- scratch (static device globals; no allocation) -------------
__device__ float g_net [(size_t)BB * C_IN * M_TOT];     // [B][130][4096] fp32
__device__ bf16  g_f16 [(size_t)BB * CQ   * M_TOT];
__device__ bf16  g_g16 [(size_t)BB * CQ   * M_TOT];
__device__ bf16  g_h16 [(size_t)BB * C_IN * M_TOT];
__device__ bf16  g_hs  [(size_t)BB * C_IN * M_TOT];     // h / Z_k (pre-scaled)
__device__ bf16  g_E   [(size_t)BB * M_TOT * M_TOT];    // 256 MB unnormalized exp(S)
__device__ float g_invZ[(size_t)BB * M_TOT];            // 1 / row sums
__device__ float g_x   [(size_t)BB * C_IN * M_TOT];
__device__ float g_x1  [(size_t)BB * 256  * M_TOT];

// ---------------- build net: tiled inputs + grid channels --------------------
__global__ void build_net(const float* __restrict__ inp) {
    int idx = blockIdx.x * blockDim.x + threadIdx.x;
    if (idx >= BB * C_IN * M_TOT) return;
    int m = idx % M_TOT;
    int c = (idx / M_TOT) % C_IN;
    int b = idx / (M_TOT * C_IN);
    float v;
    if (c < 128) {
        v = inp[((size_t)b * 128 + c) * N_PTS + (m & (N_PTS - 1))];
    } else {
        int u = m >> 10;
        if (c == 128) v = (u & 2) ? 0.2f : -0.2f;
        else          v = (u & 1) ? 0.2f : -0.2f;
    }
    g_net[idx] = v;
}

// ---------------- generic conv1x1 + relu (fp32 compute, OutT store) ----------
template <typename OutT>
__global__ __launch_bounds__(256)
void gemm_relu(const float* __restrict__ W, const float* __restrict__ bias,
               const float* __restrict__ X, OutT* __restrict__ Y,
               int O, int K) {
    __shared__ float As[16][68];
    __shared__ float Bs[16][64];
    int b  = blockIdx.z;
    const float* Xb = X + (size_t)b * K * M_TOT;
    OutT*        Yb = Y + (size_t)b * O * M_TOT;
    int o0 = blockIdx.y * 64, m0 = blockIdx.x * 64;
    int tid = threadIdx.x, tx = tid & 15, ty = tid >> 4;
    float acc[4][4] = {};
    for (int k0 = 0; k0 < K; k0 += 16) {
        #pragma unroll
        for (int i = 0; i < 4; i++) {
            int t = tid + i * 256;
            int ro = t >> 4, rk = t & 15;
            int oo = o0 + ro, kk = k0 + rk;
            As[rk][ro] = (oo < O && kk < K) ? W[(size_t)oo * K + kk] : 0.f;
        }
        {
            int rk = tid >> 4, cm = (tid & 15) * 4;
            int kk = k0 + rk;
            float4 v = make_float4(0.f, 0.f, 0.f, 0.f);
            if (kk < K) v = *(const float4*)&Xb[(size_t)kk * M_TOT + m0 + cm];
            *(float4*)&Bs[rk][cm] = v;
        }
        __syncthreads();
        #pragma unroll
        for (int kk = 0; kk < 16; kk++) {
            float a[4], bv[4];
            *(float4*)a  = *(const float4*)&As[kk][ty * 4];
            *(float4*)bv = *(const float4*)&Bs[kk][tx * 4];
            #pragma unroll
            for (int i = 0; i < 4; i++)
                #pragma unroll
                for (int j = 0; j < 4; j++) acc[i][j] += a[i] * bv[j];
        }
        __syncthreads();
    }
    #pragma unroll
    for (int i = 0; i < 4; i++) {
        int oo = o0 + ty * 4 + i;
        if (oo < O) {
            float bvv = bias[oo];
            float r0 = fmaxf(acc[i][0] + bvv, 0.f);
            float r1 = fmaxf(acc[i][1] + bvv, 0.f);
            float r2 = fmaxf(acc[i][2] + bvv, 0.f);
            float r3 = fmaxf(acc[i][3] + bvv, 0.f);
            size_t base = (size_t)oo * M_TOT + m0 + tx * 4;
            Yb[base + 0] = (OutT)r0;
            Yb[base + 1] = (OutT)r1;
            Yb[base + 2] = (OutT)r2;
            Yb[base + 3] = (OutT)r3;
        }
    }
}

// ---------------- Ẽ = exp(g^T f), wmma bf16 (K=32), 64(k) x 128(m) tile ------
// A col-major = g natural layout [c][k]; B row-major = f natural layout [c][m].
// Epilogue applies exp() and stores bf16 via smem (unnormalized softmax numer).
__global__ __launch_bounds__(256)
void s_exp() {
    __shared__ float Ss[64][132];
    int b = blockIdx.z;
    const bf16* gb = g_g16 + (size_t)b * CQ * M_TOT;
    const bf16* fb = g_f16 + (size_t)b * CQ * M_TOT;
    bf16*       Eb = g_E   + (size_t)b * M_TOT * M_TOT;
    int k0 = blockIdx.y * 64, m0 = blockIdx.x * 128;
    int tid = threadIdx.x, warp = tid >> 5;
    int wk = warp >> 2;   // 2 warp rows (32 k each)
    int wm = warp & 3;    // 4 warp cols (32 m each)

    wmma::fragment<wmma::accumulator, 16, 16, 16, float> acc[2][2];
    #pragma unroll
    for (int i = 0; i < 2; i++)
        #pragma unroll
        for (int j = 0; j < 2; j++) wmma::fill_fragment(acc[i][j], 0.f);

    #pragma unroll
    for (int cs = 0; cs < 2; cs++) {
        wmma::fragment<wmma::matrix_a, 16, 16, 16, bf16, wmma::col_major> a[2];
        wmma::fragment<wmma::matrix_b, 16, 16, 16, bf16, wmma::row_major> bt[2];
        #pragma unroll
        for (int i = 0; i < 2; i++)
            wmma::load_matrix_sync(a[i],
                gb + (size_t)(cs * 16) * M_TOT + k0 + wk * 32 + i * 16, M_TOT);
        #pragma unroll
        for (int j = 0; j < 2; j++)
            wmma::load_matrix_sync(bt[j],
                fb + (size_t)(cs * 16) * M_TOT + m0 + wm * 32 + j * 16, M_TOT);
        #pragma unroll
        for (int i = 0; i < 2; i++)
            #pragma unroll
            for (int j = 0; j < 2; j++)
                wmma::mma_sync(acc[i][j], a[i], bt[j], acc[i][j]);
    }
    #pragma unroll
    for (int i = 0; i < 2; i++)
        #pragma unroll
        for (int j = 0; j < 2; j++) {
            #pragma unroll
            for (int t = 0; t < acc[i][j].num_elements; t++)
                acc[i][j].x[t] = __expf(acc[i][j].x[t]);
            wmma::store_matrix_sync(&Ss[wk * 32 + i * 16][wm * 32 + j * 16],
                                    acc[i][j], 132, wmma::mem_row_major);
        }
    __syncthreads();
    // 64 x 128 fp32 -> bf16 gmem; 2048 groups of 4, 8 per thread
    #pragma unroll
    for (int gidx = 0; gidx < 8; gidx++) {
        int g = tid + gidx * 256;
        int row = g >> 5, c4 = (g & 31) * 4;
        float4 v = *(float4*)&Ss[row][c4];
        __nv_bfloat162 lo = __floats2bfloat162_rn(v.x, v.y);
        __nv_bfloat162 hi = __floats2bfloat162_rn(v.z, v.w);
        uint2 u = make_uint2(*(unsigned*)&lo, *(unsigned*)&hi);
        *(uint2*)&Eb[(size_t)(k0 + row) * M_TOT + m0 + c4] = u;
    }
}

// ---------------- invZ[k] = 1 / sum_m E[k][m] ---------------------------------
__global__ __launch_bounds__(256)
void z_reduce() {
    size_t row = blockIdx.x;
    const __nv_bfloat162* p = (const __nv_bfloat162*)(g_E + row * M_TOT);
    int tid = threadIdx.x;
    float s = 0.f;
    #pragma unroll
    for (int j = 0; j < 8; j++) {
        float2 f = __bfloat1622float2(p[tid + j * 256]);
        s += f.x + f.y;
    }
    __shared__ float red[256];
    red[tid] = s; __syncthreads();
    #pragma unroll
    for (int st = 128; st > 0; st >>= 1) {
        if (tid < st) red[tid] += red[tid + st];
        __syncthreads();
    }
    if (tid == 0) g_invZ[row] = 1.0f / red[0];
}

// ---------------- h' = h * invZ (fold softmax denominator into h) -------------
__global__ void h_scale() {
    int idx = blockIdx.x * blockDim.x + threadIdx.x;
    const int total = BB * C_IN * (M_TOT / 2);
    if (idx >= total) return;
    int k2 = idx % (M_TOT / 2);
    int b  = idx / (C_IN * (M_TOT / 2));
    float2 iz = *(float2*)&g_invZ[(size_t)b * M_TOT + k2 * 2];
    float2 hf = __bfloat1622float2(((const __nv_bfloat162*)g_h16)[idx]);
    ((__nv_bfloat162*)g_hs)[idx] = __floats2bfloat162_rn(hf.x * iz.x, hf.y * iz.y);
}

// ---------------- hot GEMM via wmma: x[0:128,:] = gamma*(h'@E) + net ----------
#define A_LD 72
#define C_LD 68
__global__ __launch_bounds__(256)
void attn_wmma(const float* __restrict__ gamma_p) {
    __shared__ __align__(16) unsigned char smem_raw[128 * C_LD * 4]; // 34816B
    bf16*  As = (bf16*)smem_raw;                 // [128][A_LD]
    bf16*  Bs = As + 128 * A_LD;                 // [64][A_LD]
    float* Cs = (float*)smem_raw;                // [128][C_LD]

    int b  = blockIdx.y;
    int m0 = blockIdx.x * 64;
    const bf16* hb = g_hs + (size_t)b * C_IN * M_TOT;
    const bf16* Eb = g_E  + (size_t)b * M_TOT * M_TOT;
    int tid = threadIdx.x, warp = tid >> 5;
    int wr = warp >> 1, wc = warp & 1;           // 4 x 2 warp grid, 32x32 tiles

    wmma::fragment<wmma::accumulator, 16, 16, 16, float> acc[2][2];
    #pragma unroll
    for (int i = 0; i < 2; i++)
        #pragma unroll
        for (int j = 0; j < 2; j++) wmma::fill_fragment(acc[i][j], 0.f);

    for (int k0 = 0; k0 < M_TOT; k0 += 64) {
        #pragma unroll
        for (int i = 0; i < 4; i++) {            // A: 128x64 bf16
            int idx = tid + i * 256;
            int row = idx >> 3, c8 = idx & 7;
            *(uint4*)&As[row * A_LD + c8 * 8] =
                *(const uint4*)&hb[(size_t)row * M_TOT + k0 + c8 * 8];
        }
        #pragma unroll
        for (int i = 0; i < 2; i++) {            // B: 64x64 bf16
            int idx = tid + i * 256;
            int row = idx >> 3, c8 = idx & 7;
            *(uint4*)&Bs[row * A_LD + c8 * 8] =
                *(const uint4*)&Eb[(size_t)(k0 + row) * M_TOT + m0 + c8 * 8];
        }
        __syncthreads();
        #pragma unroll
        for (int ks = 0; ks < 4; ks++) {
            wmma::fragment<wmma::matrix_a, 16, 16, 16, bf16, wmma::row_major> a[2];
            wmma::fragment<wmma::matrix_b, 16, 16, 16, bf16, wmma::row_major> bt[2];
            #pragma unroll
            for (int i = 0; i < 2; i++)
                wmma::load_matrix_sync(a[i], &As[(wr * 32 + i * 16) * A_LD + ks * 16], A_LD);
            #pragma unroll
            for (int j = 0; j < 2; j++)
                wmma::load_matrix_sync(bt[j], &Bs[(ks * 16) * A_LD + wc * 32 + j * 16], A_LD);
            #pragma unroll
            for (int i = 0; i < 2; i++)
                #pragma unroll
                for (int j = 0; j < 2; j++)
                    wmma::mma_sync(acc[i][j], a[i], bt[j], acc[i][j]);
        }
        __syncthreads();
    }

    float gamma = __ldg(gamma_p);
    #pragma unroll
    for (int i = 0; i < 2; i++)
        #pragma unroll
        for (int j = 0; j < 2; j++) {
            #pragma unroll
            for (int t = 0; t < acc[i][j].num_elements; t++)
                acc[i][j].x[t] *= gamma;
            wmma::store_matrix_sync(&Cs[(wr * 32 + i * 16) * C_LD + wc * 32 + j * 16],
                                    acc[i][j], C_LD, wmma::mem_row_major);
        }
    __syncthreads();

    const float* netb = g_net + (size_t)b * C_IN * M_TOT;
    float*       xb   = g_x   + (size_t)b * C_IN * M_TOT;
    int col = (tid & 15) * 4, r0 = tid >> 4;
    #pragma unroll
    for (int i = 0; i < 8; i++) {
        int r = r0 + i * 16;
        float4 cv = *(float4*)&Cs[r * C_LD + col];
        float4 nv = *(const float4*)&netb[(size_t)r * M_TOT + m0 + col];
        float4 o;
        o.x = cv.x + nv.x; o.y = cv.y + nv.y;
        o.z = cv.z + nv.z; o.w = cv.w + nv.w;
        *(float4*)&xb[(size_t)r * M_TOT + m0 + col] = o;
    }
}

// ---------------- tail rows 128,129: memory-bound rank-2 over E ---------------
__global__ __launch_bounds__(128)
void attn_tail(const float* __restrict__ gamma_p) {
    __shared__ float h0s[M_TOT];
    __shared__ float h1s[M_TOT];
    int b   = blockIdx.y;
    int tid = threadIdx.x;
    int m   = (blockIdx.x * 128 + tid) * 2;
    const bf16* hb = g_hs + (size_t)b * C_IN * M_TOT;
    const bf16* Eb = g_E  + (size_t)b * M_TOT * M_TOT;
    for (int i = tid; i < M_TOT; i += 128) {
        h0s[i] = __bfloat162float(hb[(size_t)128 * M_TOT + i]);
        h1s[i] = __bfloat162float(hb[(size_t)129 * M_TOT + i]);
    }
    __syncthreads();
    float a00 = 0.f, a01 = 0.f, a10 = 0.f, a11 = 0.f;
    const __nv_bfloat162* ep = (const __nv_bfloat162*)(Eb + m);
    #pragma unroll 8
    for (int k = 0; k < M_TOT; k++) {
        float2 ef = __bfloat1622float2(ep[(size_t)k * (M_TOT / 2)]);
        a00 += h0s[k] * ef.x; a01 += h0s[k] * ef.y;
        a10 += h1s[k] * ef.x; a11 += h1s[k] * ef.y;
    }
    float gamma = __ldg(gamma_p);
    const float* netb = g_net + (size_t)b * C_IN * M_TOT;
    float*       xb   = g_x   + (size_t)b * C_IN * M_TOT;
    xb[(size_t)128 * M_TOT + m]     = gamma * a00 + netb[(size_t)128 * M_TOT + m];
    xb[(size_t)128 * M_TOT + m + 1] = gamma * a01 + netb[(size_t)128 * M_TOT + m + 1];
    xb[(size_t)129 * M_TOT + m]     = gamma * a10 + netb[(size_t)129 * M_TOT + m];
    xb[(size_t)129 * M_TOT + m + 1] = gamma * a11 + netb[(size_t)129 * M_TOT + m + 1];
}

// ---------------- launch ------------------------------------------------------
extern "C" void kernel_launch(void* const* d_in, const int* in_sizes, int n_in,
                              void* d_out, int out_size) {
    const float* inputs = (const float*)d_in[0];
    const float* WF = (const float*)d_in[1];
    const float* bF = (const float*)d_in[2];
    const float* WG = (const float*)d_in[3];
    const float* bG = (const float*)d_in[4];
    const float* WH = (const float*)d_in[5];
    const float* bH = (const float*)d_in[6];
    const float* gamma = (const float*)d_in[7];
    const float* W1 = (const float*)d_in[8];
    const float* b1 = (const float*)d_in[9];
    const float* W2 = (const float*)d_in[10];
    const float* b2 = (const float*)d_in[11];
    float* out = (float*)d_out;

    void *pnet, *pf, *pg, *ph, *px, *px1;
    cudaGetSymbolAddress(&pnet, g_net);
    cudaGetSymbolAddress(&pf,   g_f16);
    cudaGetSymbolAddress(&pg,   g_g16);
    cudaGetSymbolAddress(&ph,   g_h16);
    cudaGetSymbolAddress(&px,   g_x);
    cudaGetSymbolAddress(&px1,  g_x1);

    dim3 blk(256);

    build_net<<<(BB * C_IN * M_TOT + 255) / 256, 256>>>(inputs);

    // f, g, h (bf16 outputs for the tensor-core stages)
    gemm_relu<bf16><<<dim3(M_TOT / 64, 1, BB), blk>>>(WF, bF, (const float*)pnet,
                                                      (bf16*)pf, CQ, C_IN);
    gemm_relu<bf16><<<dim3(M_TOT / 64, 1, BB), blk>>>(WG, bG, (const float*)pnet,
                                                      (bf16*)pg, CQ, C_IN);
    gemm_relu<bf16><<<dim3(M_TOT / 64, 3, BB), blk>>>(WH, bH, (const float*)pnet,
                                                      (bf16*)ph, C_IN, C_IN);

    // Ẽ = exp(g^T f) unnormalized (tensor cores + fused exp epilogue)
    s_exp<<<dim3(M_TOT / 128, M_TOT / 64, BB), blk>>>();

    // row sums -> invZ, then fold into h
    z_reduce<<<BB * M_TOT, 256>>>();
    h_scale<<<(BB * C_IN * (M_TOT / 2) + 255) / 256, 256>>>();

    // x = gamma * (h' @ Ẽ) + net  (tensor cores) + 2-row tail
    attn_wmma<<<dim3(M_TOT / 64, BB), blk>>>(gamma);
    attn_tail<<<dim3(M_TOT / 256, BB), 128>>>(gamma);

    // epilogue convs (fp32)
    gemm_relu<float><<<dim3(M_TOT / 64, 4, BB), blk>>>(W1, b1, (const float*)px,
                                                       (float*)px1, 256, C_IN);
    gemm_relu<float><<<dim3(M_TOT / 64, 2, BB), blk>>>(W2, b2, (const float*)px1,
                                                       out, 128, 256);
}

// round 15
// speedup vs baseline: 1.8915x; 1.0864x over previous
#include <cuda_runtime.h>
#include <cuda_bf16.h>
#include <mma.h>
#include <cstdint>

using namespace nvcuda;

#define BB 8
#define C_IN 130
#define N_PTS 1024
#define M_TOT 4096
#define CQ 32

typedef __nv_bfloat16 bf16;

// ---------------- scratch (static device globals; no allocation) -------------
__device__ float g_net [(size_t)BB * C_IN * M_TOT];     // [B][130][4096] fp32
__device__ bf16  g_f16 [(size_t)BB * CQ   * M_TOT];
__device__ bf16  g_g16 [(size_t)BB * CQ   * M_TOT];
__device__ bf16  g_h16 [(size_t)BB * C_IN * M_TOT];
__device__ bf16  g_hs  [(size_t)BB * C_IN * M_TOT];     // h / Z_k (pre-scaled)
__device__ bf16  g_E   [(size_t)BB * M_TOT * M_TOT];    // 256 MB unnormalized exp(S)
__device__ float g_Z   [(size_t)BB * M_TOT];            // row sums (atomic accum)
__device__ float g_x   [(size_t)BB * C_IN * M_TOT];
__device__ float g_x1  [(size_t)BB * 256  * M_TOT];

// ---------------- build net: tiled inputs + grid channels --------------------
__global__ void build_net(const float* __restrict__ inp) {
    int idx = blockIdx.x * blockDim.x + threadIdx.x;
    if (idx >= BB * C_IN * M_TOT) return;
    int m = idx % M_TOT;
    int c = (idx / M_TOT) % C_IN;
    int b = idx / (M_TOT * C_IN);
    float v;
    if (c < 128) {
        v = inp[((size_t)b * 128 + c) * N_PTS + (m & (N_PTS - 1))];
    } else {
        int u = m >> 10;
        if (c == 128) v = (u & 2) ? 0.2f : -0.2f;
        else          v = (u & 1) ? 0.2f : -0.2f;
    }
    g_net[idx] = v;
}

// ---------------- generic conv1x1 + relu (fp32 compute, OutT store) ----------
template <typename OutT>
__global__ __launch_bounds__(256)
void gemm_relu(const float* __restrict__ W, const float* __restrict__ bias,
               const float* __restrict__ X, OutT* __restrict__ Y,
               int O, int K) {
    __shared__ float As[16][68];
    __shared__ float Bs[16][64];
    int b  = blockIdx.z;
    const float* Xb = X + (size_t)b * K * M_TOT;
    OutT*        Yb = Y + (size_t)b * O * M_TOT;
    int o0 = blockIdx.y * 64, m0 = blockIdx.x * 64;
    int tid = threadIdx.x, tx = tid & 15, ty = tid >> 4;
    float acc[4][4] = {};
    for (int k0 = 0; k0 < K; k0 += 16) {
        #pragma unroll
        for (int i = 0; i < 4; i++) {
            int t = tid + i * 256;
            int ro = t >> 4, rk = t & 15;
            int oo = o0 + ro, kk = k0 + rk;
            As[rk][ro] = (oo < O && kk < K) ? W[(size_t)oo * K + kk] : 0.f;
        }
        {
            int rk = tid >> 4, cm = (tid & 15) * 4;
            int kk = k0 + rk;
            float4 v = make_float4(0.f, 0.f, 0.f, 0.f);
            if (kk < K) v = *(const float4*)&Xb[(size_t)kk * M_TOT + m0 + cm];
            *(float4*)&Bs[rk][cm] = v;
        }
        __syncthreads();
        #pragma unroll
        for (int kk = 0; kk < 16; kk++) {
            float a[4], bv[4];
            *(float4*)a  = *(const float4*)&As[kk][ty * 4];
            *(float4*)bv = *(const float4*)&Bs[kk][tx * 4];
            #pragma unroll
            for (int i = 0; i < 4; i++)
                #pragma unroll
                for (int j = 0; j < 4; j++) acc[i][j] += a[i] * bv[j];
        }
        __syncthreads();
    }
    #pragma unroll
    for (int i = 0; i < 4; i++) {
        int oo = o0 + ty * 4 + i;
        if (oo < O) {
            float bvv = bias[oo];
            float r0 = fmaxf(acc[i][0] + bvv, 0.f);
            float r1 = fmaxf(acc[i][1] + bvv, 0.f);
            float r2 = fmaxf(acc[i][2] + bvv, 0.f);
            float r3 = fmaxf(acc[i][3] + bvv, 0.f);
            size_t base = (size_t)oo * M_TOT + m0 + tx * 4;
            Yb[base + 0] = (OutT)r0;
            Yb[base + 1] = (OutT)r1;
            Yb[base + 2] = (OutT)r2;
            Yb[base + 3] = (OutT)r3;
        }
    }
}

// ---------------- Ẽ = exp(g^T f), wmma bf16 (K=32), 64(k) x 128(m) tile ------
// Epilogue: exp(), bf16 store, AND per-row partial sums -> atomicAdd g_Z.
__global__ __launch_bounds__(256)
void s_exp() {
    __shared__ float Ss[64][132];
    int b = blockIdx.z;
    const bf16* gb = g_g16 + (size_t)b * CQ * M_TOT;
    const bf16* fb = g_f16 + (size_t)b * CQ * M_TOT;
    bf16*       Eb = g_E   + (size_t)b * M_TOT * M_TOT;
    int k0 = blockIdx.y * 64, m0 = blockIdx.x * 128;
    int tid = threadIdx.x, warp = tid >> 5;
    int wk = warp >> 2;   // 2 warp rows (32 k each)
    int wm = warp & 3;    // 4 warp cols (32 m each)

    wmma::fragment<wmma::accumulator, 16, 16, 16, float> acc[2][2];
    #pragma unroll
    for (int i = 0; i < 2; i++)
        #pragma unroll
        for (int j = 0; j < 2; j++) wmma::fill_fragment(acc[i][j], 0.f);

    #pragma unroll
    for (int cs = 0; cs < 2; cs++) {
        wmma::fragment<wmma::matrix_a, 16, 16, 16, bf16, wmma::col_major> a[2];
        wmma::fragment<wmma::matrix_b, 16, 16, 16, bf16, wmma::row_major> bt[2];
        #pragma unroll
        for (int i = 0; i < 2; i++)
            wmma::load_matrix_sync(a[i],
                gb + (size_t)(cs * 16) * M_TOT + k0 + wk * 32 + i * 16, M_TOT);
        #pragma unroll
        for (int j = 0; j < 2; j++)
            wmma::load_matrix_sync(bt[j],
                fb + (size_t)(cs * 16) * M_TOT + m0 + wm * 32 + j * 16, M_TOT);
        #pragma unroll
        for (int i = 0; i < 2; i++)
            #pragma unroll
            for (int j = 0; j < 2; j++)
                wmma::mma_sync(acc[i][j], a[i], bt[j], acc[i][j]);
    }
    #pragma unroll
    for (int i = 0; i < 2; i++)
        #pragma unroll
        for (int j = 0; j < 2; j++) {
            #pragma unroll
            for (int t = 0; t < acc[i][j].num_elements; t++)
                acc[i][j].x[t] = __expf(acc[i][j].x[t]);
            wmma::store_matrix_sync(&Ss[wk * 32 + i * 16][wm * 32 + j * 16],
                                    acc[i][j], 132, wmma::mem_row_major);
        }
    __syncthreads();
    // 64 x 128 fp32 -> bf16 gmem
    #pragma unroll
    for (int gidx = 0; gidx < 8; gidx++) {
        int g = tid + gidx * 256;
        int row = g >> 5, c4 = (g & 31) * 4;
        float4 v = *(float4*)&Ss[row][c4];
        __nv_bfloat162 lo = __floats2bfloat162_rn(v.x, v.y);
        __nv_bfloat162 hi = __floats2bfloat162_rn(v.z, v.w);
        uint2 u = make_uint2(*(unsigned*)&lo, *(unsigned*)&hi);
        *(uint2*)&Eb[(size_t)(k0 + row) * M_TOT + m0 + c4] = u;
    }
    // partial row sums: 64 rows x 4 segments of 32 cols
    {
        int row = tid >> 2, seg = tid & 3;
        float s = 0.f;
        #pragma unroll
        for (int c = 0; c < 32; c++) s += Ss[row][seg * 32 + c];
        atomicAdd(&g_Z[(size_t)b * M_TOT + k0 + row], s);
    }
}

// ---------------- h' = h / Z (fold softmax denominator into h) ----------------
__global__ void h_scale() {
    int idx = blockIdx.x * blockDim.x + threadIdx.x;
    const int total = BB * C_IN * (M_TOT / 2);
    if (idx >= total) return;
    int k2 = idx % (M_TOT / 2);
    int b  = idx / (C_IN * (M_TOT / 2));
    float2 zz = *(float2*)&g_Z[(size_t)b * M_TOT + k2 * 2];
    float2 hf = __bfloat1622float2(((const __nv_bfloat162*)g_h16)[idx]);
    ((__nv_bfloat162*)g_hs)[idx] =
        __floats2bfloat162_rn(hf.x * (1.0f / zz.x), hf.y * (1.0f / zz.y));
}

// ---------------- hot GEMM: x[0:128,:] = gamma*(h'@E) + net -------------------
// 128x128 block tile, k-chunk 64, cp.async double-buffered, 8 warps (4x2).
#define ALD2 72                            // A smem ld (halfwords)
#define BLD2 136                           // B smem ld (halfwords)
#define CLD2 132                           // C smem ld (floats)
#define ABYTES (128 * ALD2 * 2)            // 18432
#define BBYTES (64 * BLD2 * 2)             // 17408
#define BUFBYTES (ABYTES + BBYTES)         // 35840
#define SMEM_ATTN (2 * BUFBYTES)           // 71680

__device__ __forceinline__ void cp16(uint32_t dst, const void* src) {
    asm volatile("cp.async.cg.shared.global [%0], [%1], 16;" :: "r"(dst), "l"(src));
}

__global__ __launch_bounds__(256)
void attn_wmma2(const float* __restrict__ gamma_p) {
    extern __shared__ __align__(16) unsigned char sm[];
    int b  = blockIdx.y;
    int m0 = blockIdx.x * 128;
    const bf16* hb = g_hs + (size_t)b * C_IN * M_TOT;
    const bf16* Eb = g_E  + (size_t)b * M_TOT * M_TOT;
    int tid = threadIdx.x, warp = tid >> 5;
    int wr = warp >> 1, wc = warp & 1;     // 4 x 2 warp grid, 32x64 per warp

    wmma::fragment<wmma::accumulator, 16, 16, 16, float> acc[2][4];
    #pragma unroll
    for (int i = 0; i < 2; i++)
        #pragma unroll
        for (int j = 0; j < 4; j++) wmma::fill_fragment(acc[i][j], 0.f);

    auto load_tile = [&](int it, int buf) {
        unsigned char* Ab = sm + buf * BUFBYTES;
        unsigned char* Bb = Ab + ABYTES;
        int k0 = it * 64;
        #pragma unroll
        for (int t = 0; t < 4; t++) {       // A: 128 x 64 bf16 = 1024 x 16B
            int idx = tid + t * 256;
            int row = idx >> 3, c8 = idx & 7;
            cp16((uint32_t)__cvta_generic_to_shared(Ab + row * (ALD2 * 2) + c8 * 16),
                 hb + (size_t)row * M_TOT + k0 + c8 * 8);
        }
        #pragma unroll
        for (int t = 0; t < 4; t++) {       // B: 64 x 128 bf16 = 1024 x 16B
            int idx = tid + t * 256;
            int row = idx >> 4, c8 = idx & 15;
            cp16((uint32_t)__cvta_generic_to_shared(Bb + row * (BLD2 * 2) + c8 * 16),
                 Eb + (size_t)(k0 + row) * M_TOT + m0 + c8 * 8);
        }
    };

    load_tile(0, 0);
    asm volatile("cp.async.commit_group;" ::: "memory");
    const int ITERS = M_TOT / 64;
    for (int it = 0; it < ITERS; it++) {
        if (it + 1 < ITERS) {
            load_tile(it + 1, (it + 1) & 1);
            asm volatile("cp.async.commit_group;" ::: "memory");
            asm volatile("cp.async.wait_group 1;" ::: "memory");
        } else {
            asm volatile("cp.async.wait_group 0;" ::: "memory");
        }
        __syncthreads();
        const bf16* As = (const bf16*)(sm + (it & 1) * BUFBYTES);
        const bf16* Bs = (const bf16*)(sm + (it & 1) * BUFBYTES + ABYTES);
        #pragma unroll
        for (int ks = 0; ks < 4; ks++) {
            wmma::fragment<wmma::matrix_a, 16, 16, 16, bf16, wmma::row_major> a[2];
            wmma::fragment<wmma::matrix_b, 16, 16, 16, bf16, wmma::row_major> bt[4];
            #pragma unroll
            for (int i = 0; i < 2; i++)
                wmma::load_matrix_sync(a[i], &As[(wr * 32 + i * 16) * ALD2 + ks * 16], ALD2);
            #pragma unroll
            for (int j = 0; j < 4; j++)
                wmma::load_matrix_sync(bt[j], &Bs[(ks * 16) * BLD2 + wc * 64 + j * 16], BLD2);
            #pragma unroll
            for (int i = 0; i < 2; i++)
                #pragma unroll
                for (int j = 0; j < 4; j++)
                    wmma::mma_sync(acc[i][j], a[i], bt[j], acc[i][j]);
        }
        __syncthreads();
    }

    float gamma = __ldg(gamma_p);
    float* Cs = (float*)sm;
    #pragma unroll
    for (int i = 0; i < 2; i++)
        #pragma unroll
        for (int j = 0; j < 4; j++) {
            #pragma unroll
            for (int t = 0; t < acc[i][j].num_elements; t++)
                acc[i][j].x[t] *= gamma;
            wmma::store_matrix_sync(&Cs[(wr * 32 + i * 16) * CLD2 + wc * 64 + j * 16],
                                    acc[i][j], CLD2, wmma::mem_row_major);
        }
    __syncthreads();

    const float* netb = g_net + (size_t)b * C_IN * M_TOT;
    float*       xb   = g_x   + (size_t)b * C_IN * M_TOT;
    int col = (tid & 31) * 4, r0 = tid >> 5;
    #pragma unroll
    for (int i = 0; i < 16; i++) {
        int r = r0 + i * 8;
        float4 cv = *(float4*)&Cs[r * CLD2 + col];
        float4 nv = *(const float4*)&netb[(size_t)r * M_TOT + m0 + col];
        float4 o;
        o.x = cv.x + nv.x; o.y = cv.y + nv.y;
        o.z = cv.z + nv.z; o.w = cv.w + nv.w;
        *(float4*)&xb[(size_t)r * M_TOT + m0 + col] = o;
    }
}

// ---------------- tail rows 128,129: memory-bound rank-2 over E ---------------
__global__ __launch_bounds__(128)
void attn_tail(const float* __restrict__ gamma_p) {
    __shared__ float h0s[M_TOT];
    __shared__ float h1s[M_TOT];
    int b   = blockIdx.y;
    int tid = threadIdx.x;
    int m   = (blockIdx.x * 128 + tid) * 2;
    const bf16* hb = g_hs + (size_t)b * C_IN * M_TOT;
    const bf16* Eb = g_E  + (size_t)b * M_TOT * M_TOT;
    for (int i = tid; i < M_TOT; i += 128) {
        h0s[i] = __bfloat162float(hb[(size_t)128 * M_TOT + i]);
        h1s[i] = __bfloat162float(hb[(size_t)129 * M_TOT + i]);
    }
    __syncthreads();
    float a00 = 0.f, a01 = 0.f, a10 = 0.f, a11 = 0.f;
    const __nv_bfloat162* ep = (const __nv_bfloat162*)(Eb + m);
    #pragma unroll 8
    for (int k = 0; k < M_TOT; k++) {
        float2 ef = __bfloat1622float2(ep[(size_t)k * (M_TOT / 2)]);
        a00 += h0s[k] * ef.x; a01 += h0s[k] * ef.y;
        a10 += h1s[k] * ef.x; a11 += h1s[k] * ef.y;
    }
    float gamma = __ldg(gamma_p);
    const float* netb = g_net + (size_t)b * C_IN * M_TOT;
    float*       xb   = g_x   + (size_t)b * C_IN * M_TOT;
    xb[(size_t)128 * M_TOT + m]     = gamma * a00 + netb[(size_t)128 * M_TOT + m];
    xb[(size_t)128 * M_TOT + m + 1] = gamma * a01 + netb[(size_t)128 * M_TOT + m + 1];
    xb[(size_t)129 * M_TOT + m]     = gamma * a10 + netb[(size_t)129 * M_TOT + m];
    xb[(size_t)129 * M_TOT + m + 1] = gamma * a11 + netb[(size_t)129 * M_TOT + m + 1];
}

// ---------------- launch ------------------------------------------------------
extern "C" void kernel_launch(void* const* d_in, const int* in_sizes, int n_in,
                              void* d_out, int out_size) {
    const float* inputs = (const float*)d_in[0];
    const float* WF = (const float*)d_in[1];
    const float* bF = (const float*)d_in[2];
    const float* WG = (const float*)d_in[3];
    const float* bG = (const float*)d_in[4];
    const float* WH = (const float*)d_in[5];
    const float* bH = (const float*)d_in[6];
    const float* gamma = (const float*)d_in[7];
    const float* W1 = (const float*)d_in[8];
    const float* b1 = (const float*)d_in[9];
    const float* W2 = (const float*)d_in[10];
    const float* b2 = (const float*)d_in[11];
    float* out = (float*)d_out;

    void *pnet, *pf, *pg, *ph, *px, *px1, *pZ;
    cudaGetSymbolAddress(&pnet, g_net);
    cudaGetSymbolAddress(&pf,   g_f16);
    cudaGetSymbolAddress(&pg,   g_g16);
    cudaGetSymbolAddress(&ph,   g_h16);
    cudaGetSymbolAddress(&px,   g_x);
    cudaGetSymbolAddress(&px1,  g_x1);
    cudaGetSymbolAddress(&pZ,   g_Z);

    cudaFuncSetAttribute(attn_wmma2,
                         cudaFuncAttributeMaxDynamicSharedMemorySize, SMEM_ATTN);

    dim3 blk(256);

    build_net<<<(BB * C_IN * M_TOT + 255) / 256, 256>>>(inputs);
    cudaMemsetAsync(pZ, 0, (size_t)BB * M_TOT * sizeof(float));

    // f, g, h (bf16 outputs for the tensor-core stages)
    gemm_relu<bf16><<<dim3(M_TOT / 64, 1, BB), blk>>>(WF, bF, (const float*)pnet,
                                                      (bf16*)pf, CQ, C_IN);
    gemm_relu<bf16><<<dim3(M_TOT / 64, 1, BB), blk>>>(WG, bG, (const float*)pnet,
                                                      (bf16*)pg, CQ, C_IN);
    gemm_relu<bf16><<<dim3(M_TOT / 64, 3, BB), blk>>>(WH, bH, (const float*)pnet,
                                                      (bf16*)ph, C_IN, C_IN);

    // Ẽ = exp(g^T f) unnormalized + fused partial row sums into g_Z
    s_exp<<<dim3(M_TOT / 128, M_TOT / 64, BB), blk>>>();

    // fold 1/Z into h
    h_scale<<<(BB * C_IN * (M_TOT / 2) + 255) / 256, 256>>>();

    // x = gamma * (h' @ Ẽ) + net  (double-buffered 128x128 wmma) + 2-row tail
    attn_wmma2<<<dim3(M_TOT / 128, BB), blk, SMEM_ATTN>>>(gamma);
    attn_tail<<<dim3(M_TOT / 256, BB), 128>>>(gamma);

    // epilogue convs (fp32)
    gemm_relu<float><<<dim3(M_TOT / 64, 4, BB), blk>>>(W1, b1, (const float*)px,
                                                       (float*)px1, 256, C_IN);
    gemm_relu<float><<<dim3(M_TOT / 64, 2, BB), blk>>>(W2, b2, (const float*)px1,
                                                       out, 128, 256);
}